// round 7
// baseline (speedup 1.0000x reference)
#include <cuda_runtime.h>
#include <cuda_bf16.h>
#include <math.h>
#include <stdint.h>

#define BB      16
#define NVV     128
#define FDD     8192
#define ROWS_TOT (BB*NVV)          // 2048 rows per tensor
#define KSPLIT  4
#define KCHUNK  (FDD/KSPLIT)       // 2048
#define NITER   (KCHUNK/64)        // 32 k-iterations of 64 bf16 cols
#define TILEB   16384              // one bf16 operand tile: 128 rows x 128 B
#define SMEM_TOT (4*TILEB)         // 2 stages x (A+B) = 64 KB

#define EPSF    1e-6f
#define CONSTE  (8192.0f*1e-6f*1e-6f)
#define TINV    5.0f
#define MARGINF 1.0f

// ---------------- device scratch (static; no runtime allocation) --------
__device__ float g_Sp[(size_t)KSPLIT*BB*NVV*NVV];      // 4 MB  q.k^T partials
__device__ float g_Lp[(size_t)KSPLIT*BB*NVV*NVV];      // 4 MB  q.n^T partials
__device__ float g_ssp[3*KSPLIT*ROWS_TOT];             // per-chunk sum(x^2) q,k,n
__device__ float g_sup[2*KSPLIT*ROWS_TOT];             // per-chunk sum(x)   q,k
__device__ float g_inv[3*ROWS_TOT];                    // inv norms q,k,n
__device__ float g_sumn[2*ROWS_TOT];                   // normalized row sums q,k
__device__ float g_parts2[BB*16*4];                    // per (batch,chunk) raw sums

// ---------------- PTX helpers (plain-sm_103-safe only) -------------------
__device__ __forceinline__ uint32_t s2u(const void* p) {
    uint32_t a;
    asm("{ .reg .u64 t; cvta.to.shared.u64 t, %1; cvt.u32.u64 %0, t; }"
        : "=r"(a) : "l"(p));
    return a;
}

// swizzle: 16B chunk c of row r placed at chunk (c ^ (r&7))
__device__ __forceinline__ uint32_t tile_off(int row, int c) {
    return (uint32_t)(row * 128 + ((c ^ (row & 7)) << 4));
}

#define LDMX4(r0, r1, r2, r3, addr) \
    asm volatile("ldmatrix.sync.aligned.m8n8.x4.shared.b16 {%0,%1,%2,%3}, [%4];" \
        : "=r"(r0), "=r"(r1), "=r"(r2), "=r"(r3) : "r"(addr))

#define MMA16816(d, a, b0, b1) \
    asm volatile("mma.sync.aligned.m16n8k16.row.col.f32.bf16.bf16.f32 " \
        "{%0,%1,%2,%3}, {%4,%5,%6,%7}, {%8,%9}, {%0,%1,%2,%3};" \
        : "+f"((d)[0]), "+f"((d)[1]), "+f"((d)[2]), "+f"((d)[3]) \
        : "r"((a)[0]), "r"((a)[1]), "r"((a)[2]), "r"((a)[3]), "r"(b0), "r"(b1))

// convert 8 fp32 -> uint4 of bf16, accumulating stats
__device__ __forceinline__ uint4 cvt8(const float4 v0, const float4 v1,
                                      float& ss, float& su) {
    ss += v0.x*v0.x + v0.y*v0.y + v0.z*v0.z + v0.w*v0.w
        + v1.x*v1.x + v1.y*v1.y + v1.z*v1.z + v1.w*v1.w;
    su += v0.x + v0.y + v0.z + v0.w + v1.x + v1.y + v1.z + v1.w;
    union { __nv_bfloat162 h[4]; uint4 u; } pk;
    pk.h[0] = __float22bfloat162_rn(make_float2(v0.x, v0.y));
    pk.h[1] = __float22bfloat162_rn(make_float2(v0.z, v0.w));
    pk.h[2] = __float22bfloat162_rn(make_float2(v1.x, v1.y));
    pk.h[3] = __float22bfloat162_rn(make_float2(v1.z, v1.w));
    return pk.u;
}

// ---------------- kernel 1: FUSED stats + convert + bf16 GEMM ------------
// grid (KSPLIT, 2, BB), 256 threads. Reads fp32 inputs directly; converts
// to bf16 in registers; accumulates per-row sum/sumsq on the fly.
// 8 warps as 2x4: warptile 64(M) x 32(N) = 4x4 m16n8k16 fragments.
__global__ __launch_bounds__(256) void mma_f(const float* __restrict__ q,
                                             const float* __restrict__ kk_,
                                             const float* __restrict__ nn_) {
    extern __shared__ char smem[];
    int tid = threadIdx.x, wid = tid >> 5, lane = tid & 31;
    int wm = wid & 1, wn = wid >> 1;      // 2 x 4 warp grid
    int kc = blockIdx.x, wh = blockIdx.y, b = blockIdx.z;
    const float* A  = q + (size_t)(b * NVV) * FDD;
    const float* Bm = (wh ? nn_ : kk_) + (size_t)(b * NVV) * FDD;
    int k0 = kc * KCHUNK;

    int row = tid >> 1, half = tid & 1;   // loader mapping: 2 threads per row
    const float* pa = A  + (size_t)row * FDD + k0 + half * 32;
    const float* pb = Bm + (size_t)row * FDD + k0 + half * 32;

    uint32_t sbase = s2u(smem);

    float acc[4][4][4];
    #pragma unroll
    for (int mi = 0; mi < 4; mi++)
        #pragma unroll
        for (int ni = 0; ni < 4; ni++)
            #pragma unroll
            for (int e = 0; e < 4; e++) acc[mi][ni][e] = 0.f;

    float ssa = 0.f, sua = 0.f, ssb = 0.f, sub = 0.f;

    // ldmatrix lane geometry (identical to round-6 proven layout)
    int a_row = wm * 64 + (lane & 15);
    int a_chi = (lane >> 4);
    int b_row = wn * 32 + (lane & 7) + ((lane & 16) ? 8 : 0);
    int b_chi = (lane >> 3) & 1;

    // prologue: stage 0 -> buffer 0
    {
        float4 fa[8], fb[8];
        #pragma unroll
        for (int i = 0; i < 8; i++) fa[i] = *(const float4*)(pa + i * 4);
        #pragma unroll
        for (int i = 0; i < 8; i++) fb[i] = *(const float4*)(pb + i * 4);
        #pragma unroll
        for (int i = 0; i < 4; i++) {
            *(uint4*)(smem + tile_off(row, half * 4 + i)) =
                cvt8(fa[2*i], fa[2*i+1], ssa, sua);
            *(uint4*)(smem + TILEB + tile_off(row, half * 4 + i)) =
                cvt8(fb[2*i], fb[2*i+1], ssb, sub);
        }
    }
    __syncthreads();

    for (int it = 0; it < NITER; it++) {
        int cur = it & 1;
        bool pre = (it + 1 < NITER);
        float4 fa[8], fb[8];
        if (pre) {
            const float* ra = pa + (it + 1) * 64;
            const float* rb = pb + (it + 1) * 64;
            #pragma unroll
            for (int i = 0; i < 8; i++) fa[i] = *(const float4*)(ra + i * 4);
            #pragma unroll
            for (int i = 0; i < 8; i++) fb[i] = *(const float4*)(rb + i * 4);
        }

        uint32_t smA = sbase + cur * (2 * TILEB);
        uint32_t smB = smA + TILEB;
        #pragma unroll
        for (int kkx = 0; kkx < 4; kkx++) {
            uint32_t af[4][4];
            #pragma unroll
            for (int mi = 0; mi < 4; mi++)
                LDMX4(af[mi][0], af[mi][1], af[mi][2], af[mi][3],
                      smA + tile_off(a_row + mi * 16, kkx * 2 + a_chi));
            uint32_t bfr[2][4];
            #pragma unroll
            for (int nh = 0; nh < 2; nh++)
                LDMX4(bfr[nh][0], bfr[nh][1], bfr[nh][2], bfr[nh][3],
                      smB + tile_off(b_row + nh * 16, kkx * 2 + b_chi));
            #pragma unroll
            for (int mi = 0; mi < 4; mi++)
                #pragma unroll
                for (int ni = 0; ni < 4; ni++)
                    MMA16816(acc[mi][ni], af[mi],
                             bfr[ni >> 1][(ni & 1) * 2], bfr[ni >> 1][(ni & 1) * 2 + 1]);
        }

        if (pre) {
            char* dA = smem + ((it + 1) & 1) * (2 * TILEB);
            char* dB = dA + TILEB;
            #pragma unroll
            for (int i = 0; i < 4; i++) {
                *(uint4*)(dA + tile_off(row, half * 4 + i)) =
                    cvt8(fa[2*i], fa[2*i+1], ssa, sua);
                *(uint4*)(dB + tile_off(row, half * 4 + i)) =
                    cvt8(fb[2*i], fb[2*i+1], ssb, sub);
            }
            __syncthreads();   // single barrier per iteration (see analysis)
        }
    }

    // ---- stats write-out: combine the two half-threads of each row ----
    ssa += __shfl_xor_sync(0xffffffffu, ssa, 1);
    sua += __shfl_xor_sync(0xffffffffu, sua, 1);
    ssb += __shfl_xor_sync(0xffffffffu, ssb, 1);
    sub += __shfl_xor_sync(0xffffffffu, sub, 1);
    if (half == 0) {
        int gr = b * NVV + row;
        if (wh == 0) {
            g_ssp[(0 * KSPLIT + kc) * ROWS_TOT + gr] = ssa;   // q
            g_sup[(0 * KSPLIT + kc) * ROWS_TOT + gr] = sua;
            g_ssp[(1 * KSPLIT + kc) * ROWS_TOT + gr] = ssb;   // k
            g_sup[(1 * KSPLIT + kc) * ROWS_TOT + gr] = sub;
        } else {
            g_ssp[(2 * KSPLIT + kc) * ROWS_TOT + gr] = ssb;   // n
        }
    }

    // ---- GEMM epilogue: write fp32 partials ----
    float* out = (wh ? g_Lp : g_Sp) + ((size_t)kc * BB + b) * (NVV * NVV);
    int gr2 = lane >> 2, tc = lane & 3;
    #pragma unroll
    for (int mi = 0; mi < 4; mi++) {
        #pragma unroll
        for (int ni = 0; ni < 4; ni++) {
            int r0 = wm * 64 + mi * 16 + gr2;
            int col = wn * 32 + ni * 8 + tc * 2;
            *(float2*)&out[(size_t)r0 * NVV + col] =
                make_float2(acc[mi][ni][0], acc[mi][ni][1]);
            *(float2*)&out[(size_t)(r0 + 8) * NVV + col] =
                make_float2(acc[mi][ni][2], acc[mi][ni][3]);
        }
    }
}

// ---------------- kernel 2: reduce per-chunk stats to inv norms ----------
__global__ __launch_bounds__(256) void stats_red_k() {
    int idx = blockIdx.x * 256 + threadIdx.x;      // 0 .. 3*ROWS_TOT-1
    if (idx >= 3 * ROWS_TOT) return;
    int t = idx / ROWS_TOT, r = idx % ROWS_TOT;
    float ss = 0.f;
    #pragma unroll
    for (int p = 0; p < KSPLIT; p++) ss += g_ssp[(t * KSPLIT + p) * ROWS_TOT + r];
    float inv = 1.f / fmaxf(sqrtf(ss), 1e-12f);
    g_inv[idx] = inv;
    if (t < 2) {
        float su = 0.f;
        #pragma unroll
        for (int p = 0; p < KSPLIT; p++) su += g_sup[(t * KSPLIT + p) * ROWS_TOT + r];
        g_sumn[t * ROWS_TOT + r] = su * inv;
    }
}

// ---------------- kernel 3: fused normalize + loss epilogue --------------
// grid (16, BB): 8 rows of the 128x128 matrices per CTA. Reads the K-split
// partials directly (L2-resident) and applies normalization inline.
__global__ __launch_bounds__(256) void epi3_k() {
    int chunk = blockIdx.x, b = blockIdx.y, tid = threadIdx.x;
    __shared__ float invq[NVV], invk[NVV], invn[NVV];
    __shared__ float sqv[NVV], skv[NVV], dqk_d[NVV], dkq_d[NVV], sdiag[NVV];

    if (tid < NVV) {
        float iq = g_inv[b * NVV + tid];
        float ik = g_inv[ROWS_TOT + b * NVV + tid];
        invq[tid] = iq; invk[tid] = ik;
        invn[tid] = g_inv[2 * ROWS_TOT + b * NVV + tid];
        float sq = g_sumn[b * NVV + tid];
        float sk = g_sumn[ROWS_TOT + b * NVV + tid];
        sqv[tid] = sq; skv[tid] = sk;
        float sr = 0.f;
        #pragma unroll
        for (int p = 0; p < KSPLIT; p++)
            sr += g_Sp[(size_t)(p * BB + b) * (NVV * NVV) + tid * (NVV + 1)];
        float Sii = sr * iq * ik;
        sdiag[tid] = Sii;
        dqk_d[tid] = sqrtf(fmaxf(2.f - 2.f * Sii + 2.f * EPSF * (sq - sk) + CONSTE, 0.f));
        dkq_d[tid] = sqrtf(fmaxf(2.f - 2.f * Sii + 2.f * EPSF * (sk - sq) + CONSTE, 0.f));
    }
    __syncthreads();

    const float* Sp0 = g_Sp + (size_t)b * (NVV * NVV);
    const float* Lp0 = g_Lp + (size_t)b * (NVV * NVV);
    const size_t PST = (size_t)BB * NVV * NVV;     // stride between K-split slabs

    float smacc = 0.f, triacc = 0.f, cycacc = 0.f, ceacc = 0.f;
    #pragma unroll
    for (int h = 0; h < 4; h++) {
        int idx = h * 256 + tid;           // 0..1023 over 8 rows x 128 cols
        int il = idx >> 7, j = idx & 127;
        int i = chunk * 8 + il;
        float sr = 0.f;
        #pragma unroll
        for (int p = 0; p < KSPLIT; p++) sr += Sp0[p * PST + i * NVV + j];
        float Sij = sr * invq[i] * invk[j];
        if (i == j) {
            float d = Sij - 1.f; smacc += d * d;
        } else {
            smacc += Sij * Sij;
            float st = 0.f;
            #pragma unroll
            for (int p = 0; p < KSPLIT; p++) st += Sp0[p * PST + j * NVV + i];
            float Sji = st * invq[j] * invk[i];
            cycacc += fabsf(Sij - Sji);
            // tri1: anc=q_i, pos=k_i, neg=k_j
            float dq = sqrtf(fmaxf(2.f - 2.f * Sij + 2.f * EPSF * (sqv[i] - skv[j]) + CONSTE, 0.f));
            triacc += fmaxf(dqk_d[i] - dq + MARGINF, 0.f);
            // tri2 reindexed over (i,j): relu(dkq[j] - d(S_ij; sk[j], sq[i]) + M)
            float dk = sqrtf(fmaxf(2.f - 2.f * Sij + 2.f * EPSF * (skv[j] - sqv[i]) + CONSTE, 0.f));
            triacc += fmaxf(dkq_d[j] - dk + MARGINF, 0.f);
        }
    }

    // InfoNCE: warp w handles row chunk*8 + w (129 logits)
    int lane = tid & 31, w = tid >> 5;
    {
        int i = chunk * 8 + w;
        float iq = invq[i];
        float lpos = sdiag[i] * TINV;
        float mx = lpos;
        float lg[4];
        #pragma unroll
        for (int m = 0; m < 4; m++) {
            int j = lane + m * 32;
            float lr = 0.f;
            #pragma unroll
            for (int p = 0; p < KSPLIT; p++) lr += Lp0[p * PST + i * NVV + j];
            lg[m] = lr * iq * invn[j] * TINV;
            mx = fmaxf(mx, lg[m]);
        }
        #pragma unroll
        for (int o = 16; o > 0; o >>= 1) mx = fmaxf(mx, __shfl_xor_sync(0xffffffffu, mx, o));
        float se = (lane == 0) ? expf(lpos - mx) : 0.f;
        #pragma unroll
        for (int m = 0; m < 4; m++) se += expf(lg[m] - mx);
        #pragma unroll
        for (int o = 16; o > 0; o >>= 1) se += __shfl_xor_sync(0xffffffffu, se, o);
        if (lane == 0) ceacc = mx + logf(se) - lpos;
    }

    __shared__ float red[4][8];
    #pragma unroll
    for (int o = 16; o > 0; o >>= 1) {
        smacc  += __shfl_xor_sync(0xffffffffu, smacc,  o);
        triacc += __shfl_xor_sync(0xffffffffu, triacc, o);
        cycacc += __shfl_xor_sync(0xffffffffu, cycacc, o);
        ceacc  += __shfl_xor_sync(0xffffffffu, ceacc,  o);
    }
    if (lane == 0) { red[0][w] = smacc; red[1][w] = triacc; red[2][w] = cycacc; red[3][w] = ceacc; }
    __syncthreads();
    if (tid == 0) {
        float a = 0.f, t = 0.f, c = 0.f, e = 0.f;
        #pragma unroll
        for (int i = 0; i < 8; i++) { a += red[0][i]; t += red[1][i]; c += red[2][i]; e += red[3][i]; }
        float* p = &g_parts2[(b * 16 + chunk) * 4];
        p[0] = a; p[1] = t; p[2] = c; p[3] = e;
    }
}

// ---------------- kernel 4: final combine (keeps the cumsum-batches bug) --
__global__ void final_k(float* out, int out_size) {
    if (threadIdx.x == 0 && blockIdx.x == 0) {
        float ssl = 0.f, tw = 0.f;
        for (int b = 0; b < BB; b++) {
            float sm = 0.f, tri = 0.f, cyc = 0.f, ce = 0.f;
            for (int c2 = 0; c2 < 16; c2++) {
                const float* p = &g_parts2[(b * 16 + c2) * 4];
                sm += p[0]; tri += p[1]; cyc += p[2]; ce += p[3];
            }
            ssl += sm / (float)(NVV * NVV) + cyc / (float)(NVV * (NVV - 1))
                 + ce / (float)(NVV * NVV);
            tw += (float)(BB - b) * tri;       // sum of cumsum
        }
        ssl += tw / (float)(2 * NVV * (NVV - 1));
        for (int i = 0; i < out_size; i++) out[i] = ssl;
    }
}

// ---------------- launch -----------------------------------------------
extern "C" void kernel_launch(void* const* d_in, const int* in_sizes, int n_in,
                              void* d_out, int out_size) {
    const float* q = (const float*)d_in[0];
    const float* k = (const float*)d_in[1];
    const float* n = (const float*)d_in[2];
    // d_in[3] = num_gt; fixed at 128 == NV for these shapes.

    cudaFuncSetAttribute(mma_f, cudaFuncAttributeMaxDynamicSharedMemorySize, SMEM_TOT);

    dim3 gg(KSPLIT, 2, BB);
    mma_f<<<gg, 256, SMEM_TOT>>>(q, k, n);
    stats_red_k<<<(3 * ROWS_TOT + 255) / 256, 256>>>();
    dim3 ge(16, BB);
    epi3_k<<<ge, 256>>>();
    final_k<<<1, 32>>>((float*)d_out, out_size);
}

// round 8
// speedup vs baseline: 1.5640x; 1.5640x over previous
#include <cuda_runtime.h>
#include <cuda_bf16.h>
#include <math.h>
#include <stdint.h>

#define BB      16
#define NVV     128
#define FDD     8192
#define ROWS_TOT (BB*NVV)          // 2048 rows per tensor
#define KSPLIT  4
#define KCHUNK  (FDD/KSPLIT)       // 2048
#define NST     4                  // cp.async pipeline stages
#define NITER   (KCHUNK/64)        // 32 k-iterations of 64 bf16
#define TILEB   16384              // one operand tile: 128 rows x 128 B
#define SMEM_TOT (2*NST*TILEB)     // 131072 B

#define EPSF    1e-6f
#define CONSTE  (8192.0f*1e-6f*1e-6f)
#define TINV    5.0f
#define MARGINF 1.0f

// ---------------- device scratch (static; no runtime allocation) --------
__device__ __nv_bfloat16 g_qb[(size_t)ROWS_TOT*FDD];   // 33.5 MB
__device__ __nv_bfloat16 g_kb[(size_t)ROWS_TOT*FDD];
__device__ __nv_bfloat16 g_nb[(size_t)ROWS_TOT*FDD];
__device__ float g_Sp[(size_t)KSPLIT*BB*NVV*NVV];      // 4 MB  q.k^T partials
__device__ float g_Lp[(size_t)KSPLIT*BB*NVV*NVV];      // 4 MB  q.n^T partials
__device__ float g_inv[3*ROWS_TOT];                    // inv norms q,k,n
__device__ float g_sumn[2*ROWS_TOT];                   // normalized row sums q,k
__device__ float g_parts2[BB*16*4];                    // per (batch,chunk) raw sums

// ---------------- PTX helpers (plain-sm_103-safe only) -------------------
__device__ __forceinline__ uint32_t s2u(const void* p) {
    uint32_t a;
    asm("{ .reg .u64 t; cvta.to.shared.u64 t, %1; cvt.u32.u64 %0, t; }"
        : "=r"(a) : "l"(p));
    return a;
}
#define CPA16(smem_u32, gptr) \
    asm volatile("cp.async.cg.shared.global [%0], [%1], 16;" \
                 :: "r"(smem_u32), "l"(gptr) : "memory")
#define CPA_COMMIT() asm volatile("cp.async.commit_group;" ::: "memory")
#define CPA_WAIT(n)  asm volatile("cp.async.wait_group %0;" :: "n"(n) : "memory")

// swizzle: 16B chunk c of row r placed at chunk (c ^ (r&7))
__device__ __forceinline__ uint32_t tile_off(int row, int c) {
    return (uint32_t)(row * 128 + ((c ^ (row & 7)) << 4));
}

#define LDMX4(r0, r1, r2, r3, addr) \
    asm volatile("ldmatrix.sync.aligned.m8n8.x4.shared.b16 {%0,%1,%2,%3}, [%4];" \
        : "=r"(r0), "=r"(r1), "=r"(r2), "=r"(r3) : "r"(addr))

#define MMA16816(d, a, b0, b1) \
    asm volatile("mma.sync.aligned.m16n8k16.row.col.f32.bf16.bf16.f32 " \
        "{%0,%1,%2,%3}, {%4,%5,%6,%7}, {%8,%9}, {%0,%1,%2,%3};" \
        : "+f"((d)[0]), "+f"((d)[1]), "+f"((d)[2]), "+f"((d)[3]) \
        : "r"((a)[0]), "r"((a)[1]), "r"((a)[2]), "r"((a)[3]), "r"(b0), "r"(b1))

// ---------------- kernel 1: fused stats + bf16 conversion ----------------
__global__ __launch_bounds__(256) void prep_k(const float* __restrict__ q,
                                              const float* __restrict__ k,
                                              const float* __restrict__ n) {
    int blk = blockIdx.x;                  // 0 .. 3*ROWS_TOT-1
    int t = blk / ROWS_TOT;
    int r = blk % ROWS_TOT;
    const float* src = (t == 0 ? q : (t == 1 ? k : n)) + (size_t)r * FDD;
    __nv_bfloat16* dst = (t == 0 ? g_qb : (t == 1 ? g_kb : g_nb)) + (size_t)r * FDD;

    float ss = 0.f, su = 0.f;
    for (int c = threadIdx.x * 8; c < FDD; c += 256 * 8) {
        float4 v0 = *(const float4*)(src + c);
        float4 v1 = *(const float4*)(src + c + 4);
        ss += v0.x*v0.x + v0.y*v0.y + v0.z*v0.z + v0.w*v0.w
            + v1.x*v1.x + v1.y*v1.y + v1.z*v1.z + v1.w*v1.w;
        su += v0.x + v0.y + v0.z + v0.w + v1.x + v1.y + v1.z + v1.w;
        union { __nv_bfloat162 h[4]; uint4 u; } pk;
        pk.h[0] = __float22bfloat162_rn(make_float2(v0.x, v0.y));
        pk.h[1] = __float22bfloat162_rn(make_float2(v0.z, v0.w));
        pk.h[2] = __float22bfloat162_rn(make_float2(v1.x, v1.y));
        pk.h[3] = __float22bfloat162_rn(make_float2(v1.z, v1.w));
        *(uint4*)(dst + c) = pk.u;
    }
    __shared__ float rs[8], ru[8];
    #pragma unroll
    for (int o = 16; o > 0; o >>= 1) {
        ss += __shfl_xor_sync(0xffffffffu, ss, o);
        su += __shfl_xor_sync(0xffffffffu, su, o);
    }
    int lane = threadIdx.x & 31, w = threadIdx.x >> 5;
    if (lane == 0) { rs[w] = ss; ru[w] = su; }
    __syncthreads();
    if (threadIdx.x == 0) {
        float S = 0.f, U = 0.f;
        #pragma unroll
        for (int i = 0; i < 8; i++) { S += rs[i]; U += ru[i]; }
        float inv = 1.f / fmaxf(sqrtf(S), 1e-12f);
        g_inv[t * ROWS_TOT + r] = inv;
        if (t < 2) g_sumn[t * ROWS_TOT + r] = U * inv;
    }
}

// ---------------- kernel 2: mma.sync bf16 GEMM partials ------------------
// grid (KSPLIT, 2, BB), 256 threads. CTA computes a 128x128 x KCHUNK chunk.
// 8 warps as 2x4: warptile 64(M) x 32(N) = 4x4 m16n8k16 fragments.
__device__ __forceinline__ void load_tile(uint32_t smA, uint32_t smB,
                                          const __nv_bfloat16* A,
                                          const __nv_bfloat16* Bm,
                                          int kelem, int tid) {
    #pragma unroll
    for (int h = 0; h < 4; h++) {
        int l = tid + h * 256;            // 0..1023 chunks of 16B
        int row = l >> 3;
        int c = l & 7;
        uint32_t off = tile_off(row, c);
        const char* ga = (const char*)(A  + (size_t)row * FDD + kelem) + c * 16;
        const char* gb = (const char*)(Bm + (size_t)row * FDD + kelem) + c * 16;
        CPA16(smA + off, ga);
        CPA16(smB + off, gb);
    }
}

__global__ __launch_bounds__(256) void mma_k() {
    extern __shared__ char smem[];
    int tid = threadIdx.x, wid = tid >> 5, lane = tid & 31;
    int wm = wid & 1, wn = wid >> 1;      // 2 x 4 warp grid
    int kc = blockIdx.x, wh = blockIdx.y, b = blockIdx.z;
    const __nv_bfloat16* A  = g_qb + (size_t)(b * NVV) * FDD;
    const __nv_bfloat16* Bm = (wh ? g_nb : g_kb) + (size_t)(b * NVV) * FDD;
    int k0 = kc * KCHUNK;

    uint32_t sbase = s2u(smem);
    uint32_t tilesA = sbase;
    uint32_t tilesB = sbase + NST * TILEB;

    float acc[4][4][4];
    #pragma unroll
    for (int mi = 0; mi < 4; mi++)
        #pragma unroll
        for (int ni = 0; ni < 4; ni++)
            #pragma unroll
            for (int e = 0; e < 4; e++) acc[mi][ni][e] = 0.f;

    int a_row = wm * 64 + (lane & 15);          // + mi*16
    int a_chi = (lane >> 4);                    // + kk*2
    int b_row = wn * 32 + (lane & 7) + ((lane & 16) ? 8 : 0);  // + nh*16
    int b_chi = (lane >> 3) & 1;                // + kk*2

    #pragma unroll
    for (int s = 0; s < NST - 1; s++) {
        load_tile(tilesA + s * TILEB, tilesB + s * TILEB, A, Bm, k0 + s * 64, tid);
        CPA_COMMIT();
    }

    for (int it = 0; it < NITER; it++) {
        int nxt = it + NST - 1;
        if (nxt < NITER) {
            int sn = nxt % NST;
            load_tile(tilesA + sn * TILEB, tilesB + sn * TILEB, A, Bm, k0 + nxt * 64, tid);
        }
        CPA_COMMIT();
        CPA_WAIT(NST - 1);                 // stage 'it' complete
        __syncthreads();

        uint32_t smA = tilesA + (it % NST) * TILEB;
        uint32_t smB = tilesB + (it % NST) * TILEB;
        #pragma unroll
        for (int kk = 0; kk < 4; kk++) {
            uint32_t af[4][4];
            #pragma unroll
            for (int mi = 0; mi < 4; mi++)
                LDMX4(af[mi][0], af[mi][1], af[mi][2], af[mi][3],
                      smA + tile_off(a_row + mi * 16, kk * 2 + a_chi));
            uint32_t bf[2][4];
            #pragma unroll
            for (int nh = 0; nh < 2; nh++)
                LDMX4(bf[nh][0], bf[nh][1], bf[nh][2], bf[nh][3],
                      smB + tile_off(b_row + nh * 16, kk * 2 + b_chi));
            #pragma unroll
            for (int mi = 0; mi < 4; mi++)
                #pragma unroll
                for (int ni = 0; ni < 4; ni++)
                    MMA16816(acc[mi][ni], af[mi],
                             bf[ni >> 1][(ni & 1) * 2], bf[ni >> 1][(ni & 1) * 2 + 1]);
        }
        __syncthreads();                   // slot reused by next iteration's load
    }

    float* out = (wh ? g_Lp : g_Sp) + ((size_t)kc * BB + b) * (NVV * NVV);
    int gr = lane >> 2, tc = lane & 3;
    #pragma unroll
    for (int mi = 0; mi < 4; mi++) {
        #pragma unroll
        for (int ni = 0; ni < 4; ni++) {
            int r0 = wm * 64 + mi * 16 + gr;
            int col = wn * 32 + ni * 8 + tc * 2;
            *(float2*)&out[(size_t)r0 * NVV + col] =
                make_float2(acc[mi][ni][0], acc[mi][ni][1]);
            *(float2*)&out[(size_t)(r0 + 8) * NVV + col] =
                make_float2(acc[mi][ni][2], acc[mi][ni][3]);
        }
    }
}

// ---------------- kernel 3: fused normalize + loss epilogue --------------
// grid (16, BB): 8 rows of the 128x128 matrices per CTA. Reads the K-split
// partials directly (L2-resident) and applies normalization inline.
__global__ __launch_bounds__(256) void epi3_k() {
    int chunk = blockIdx.x, b = blockIdx.y, tid = threadIdx.x;
    __shared__ float invq[NVV], invk[NVV], invn[NVV];
    __shared__ float sqv[NVV], skv[NVV], dqk_d[NVV], dkq_d[NVV], sdiag[NVV];

    if (tid < NVV) {
        float iq = g_inv[b * NVV + tid];
        float ik = g_inv[ROWS_TOT + b * NVV + tid];
        invq[tid] = iq; invk[tid] = ik;
        invn[tid] = g_inv[2 * ROWS_TOT + b * NVV + tid];
        float sq = g_sumn[b * NVV + tid];
        float sk = g_sumn[ROWS_TOT + b * NVV + tid];
        sqv[tid] = sq; skv[tid] = sk;
        float sr = 0.f;
        #pragma unroll
        for (int p = 0; p < KSPLIT; p++)
            sr += g_Sp[(size_t)(p * BB + b) * (NVV * NVV) + tid * (NVV + 1)];
        float Sii = sr * iq * ik;
        sdiag[tid] = Sii;
        dqk_d[tid] = sqrtf(fmaxf(2.f - 2.f * Sii + 2.f * EPSF * (sq - sk) + CONSTE, 0.f));
        dkq_d[tid] = sqrtf(fmaxf(2.f - 2.f * Sii + 2.f * EPSF * (sk - sq) + CONSTE, 0.f));
    }
    __syncthreads();

    const float* Sp0 = g_Sp + (size_t)b * (NVV * NVV);
    const float* Lp0 = g_Lp + (size_t)b * (NVV * NVV);
    const size_t PST = (size_t)BB * NVV * NVV;     // stride between K-split slabs

    float smacc = 0.f, triacc = 0.f, cycacc = 0.f, ceacc = 0.f;
    #pragma unroll
    for (int h = 0; h < 4; h++) {
        int idx = h * 256 + tid;           // 0..1023 over 8 rows x 128 cols
        int il = idx >> 7, j = idx & 127;
        int i = chunk * 8 + il;
        float sr = 0.f;
        #pragma unroll
        for (int p = 0; p < KSPLIT; p++) sr += Sp0[p * PST + i * NVV + j];
        float Sij = sr * invq[i] * invk[j];
        if (i == j) {
            float d = Sij - 1.f; smacc += d * d;
        } else {
            smacc += Sij * Sij;
            float st = 0.f;
            #pragma unroll
            for (int p = 0; p < KSPLIT; p++) st += Sp0[p * PST + j * NVV + i];
            float Sji = st * invq[j] * invk[i];
            cycacc += fabsf(Sij - Sji);
            // tri1: anc=q_i, pos=k_i, neg=k_j
            float dq = sqrtf(fmaxf(2.f - 2.f * Sij + 2.f * EPSF * (sqv[i] - skv[j]) + CONSTE, 0.f));
            triacc += fmaxf(dqk_d[i] - dq + MARGINF, 0.f);
            // tri2 reindexed over (i,j): relu(dkq[j] - d(S_ij; sk[j], sq[i]) + M)
            float dk = sqrtf(fmaxf(2.f - 2.f * Sij + 2.f * EPSF * (skv[j] - sqv[i]) + CONSTE, 0.f));
            triacc += fmaxf(dkq_d[j] - dk + MARGINF, 0.f);
        }
    }

    // InfoNCE: warp w handles row chunk*8 + w (129 logits)
    int lane = tid & 31, w = tid >> 5;
    {
        int i = chunk * 8 + w;
        float iq = invq[i];
        float lpos = sdiag[i] * TINV;
        float mx = lpos;
        float lg[4];
        #pragma unroll
        for (int m = 0; m < 4; m++) {
            int j = lane + m * 32;
            float lr = 0.f;
            #pragma unroll
            for (int p = 0; p < KSPLIT; p++) lr += Lp0[p * PST + i * NVV + j];
            lg[m] = lr * iq * invn[j] * TINV;
            mx = fmaxf(mx, lg[m]);
        }
        #pragma unroll
        for (int o = 16; o > 0; o >>= 1) mx = fmaxf(mx, __shfl_xor_sync(0xffffffffu, mx, o));
        float se = (lane == 0) ? expf(lpos - mx) : 0.f;
        #pragma unroll
        for (int m = 0; m < 4; m++) se += expf(lg[m] - mx);
        #pragma unroll
        for (int o = 16; o > 0; o >>= 1) se += __shfl_xor_sync(0xffffffffu, se, o);
        if (lane == 0) ceacc = mx + logf(se) - lpos;
    }

    __shared__ float red[4][8];
    #pragma unroll
    for (int o = 16; o > 0; o >>= 1) {
        smacc  += __shfl_xor_sync(0xffffffffu, smacc,  o);
        triacc += __shfl_xor_sync(0xffffffffu, triacc, o);
        cycacc += __shfl_xor_sync(0xffffffffu, cycacc, o);
        ceacc  += __shfl_xor_sync(0xffffffffu, ceacc,  o);
    }
    if (lane == 0) { red[0][w] = smacc; red[1][w] = triacc; red[2][w] = cycacc; red[3][w] = ceacc; }
    __syncthreads();
    if (tid == 0) {
        float a = 0.f, t = 0.f, c = 0.f, e = 0.f;
        #pragma unroll
        for (int i = 0; i < 8; i++) { a += red[0][i]; t += red[1][i]; c += red[2][i]; e += red[3][i]; }
        float* p = &g_parts2[(b * 16 + chunk) * 4];
        p[0] = a; p[1] = t; p[2] = c; p[3] = e;
    }
}

// ---------------- kernel 4: parallel final combine ------------------------
// 256 threads reduce the 1024 weighted g_parts2 entries (weights encode the
// reference's cumsum-across-batches tri bug), then fan out the output write.
__global__ __launch_bounds__(256) void final2_k(float* out, int out_size) {
    int tid = threadIdx.x;
    float acc = 0.f;
    #pragma unroll
    for (int h = 0; h < 4; h++) {
        int e = h * 256 + tid;             // 0..1023 over (b, chunk, comp)
        int b = e >> 6;                    // 16 chunks * 4 comps = 64 per batch
        int comp = e & 3;
        float p = g_parts2[e];
        float w;
        if (comp == 1)      w = (float)(BB - b) / (float)(2 * NVV * (NVV - 1));
        else if (comp == 2) w = 1.f / (float)(NVV * (NVV - 1));
        else                w = 1.f / (float)(NVV * NVV);
        acc += w * p;
    }
    __shared__ float red[8];
    int lane = tid & 31, w = tid >> 5;
    #pragma unroll
    for (int o = 16; o > 0; o >>= 1) acc += __shfl_xor_sync(0xffffffffu, acc, o);
    if (lane == 0) red[w] = acc;
    __syncthreads();
    __shared__ float s_ssl;
    if (tid == 0) {
        float t = 0.f;
        #pragma unroll
        for (int i = 0; i < 8; i++) t += red[i];
        s_ssl = t;
    }
    __syncthreads();
    float v = s_ssl;
    for (int i = tid; i < out_size; i += 256) out[i] = v;
}

// ---------------- launch -----------------------------------------------
extern "C" void kernel_launch(void* const* d_in, const int* in_sizes, int n_in,
                              void* d_out, int out_size) {
    const float* q = (const float*)d_in[0];
    const float* k = (const float*)d_in[1];
    const float* n = (const float*)d_in[2];
    // d_in[3] = num_gt; fixed at 128 == NV for these shapes.

    cudaFuncSetAttribute(mma_k, cudaFuncAttributeMaxDynamicSharedMemorySize, SMEM_TOT);

    prep_k<<<3 * ROWS_TOT, 256>>>(q, k, n);
    dim3 gg(KSPLIT, 2, BB);
    mma_k<<<gg, 256, SMEM_TOT>>>();
    dim3 ge(16, BB);
    epi3_k<<<ge, 256>>>();
    final2_k<<<1, 256>>>((float*)d_out, out_size);
}

// round 9
// speedup vs baseline: 2.0447x; 1.3074x over previous
#include <cuda_runtime.h>
#include <cuda_bf16.h>
#include <math.h>
#include <stdint.h>

#define BB      16
#define NVV     128
#define FDD     8192
#define ROWS_TOT (BB*NVV)          // 2048 rows per tensor
#define KSPLIT  8
#define KCHUNK  (FDD/KSPLIT)       // 1024
#define SLAB    32                 // k-columns per iteration
#define NITER   (KCHUNK/SLAB)      // 32
#define NSTG    3                  // cp.async fp32 stages

// SMEM layout (dynamic):
//   fp32 stages: NSTG x 3 ops x 16384 B (128 rows x 32 fp32, swizzled 16B chunks)
//   bf16 tiles : 3 ops x 16384 B (128-B rows, logical chunks 0..3, swizzled)
//   stats      : 5 x 256 floats
#define F32OP   16384
#define OFF_B16 (NSTG*3*F32OP)             // 147456
#define OFF_STAT (OFF_B16 + 3*16384)       // 196608
#define SMEM_TOT (OFF_STAT + 5*256*4)      // 201728

#define EPSF    1e-6f
#define CONSTE  (8192.0f*1e-6f*1e-6f)
#define TINV    5.0f
#define MARGINF 1.0f

// ---------------- device scratch (static; no runtime allocation) --------
__device__ float g_Sp[(size_t)KSPLIT*BB*NVV*NVV];      // 8 MB  q.k^T partials
__device__ float g_Lp[(size_t)KSPLIT*BB*NVV*NVV];      // 8 MB  q.n^T partials
__device__ float g_ssp[3*KSPLIT*ROWS_TOT];             // per-chunk sum(x^2) q,k,n
__device__ float g_sup[2*KSPLIT*ROWS_TOT];             // per-chunk sum(x)   q,k
__device__ float g_parts2[BB*16*4];                    // per (batch,chunk) raw sums

// ---------------- PTX helpers (plain-sm_103-safe only) -------------------
__device__ __forceinline__ uint32_t s2u(const void* p) {
    uint32_t a;
    asm("{ .reg .u64 t; cvta.to.shared.u64 t, %1; cvt.u32.u64 %0, t; }"
        : "=r"(a) : "l"(p));
    return a;
}
#define CPA16(smem_u32, gptr) \
    asm volatile("cp.async.cg.shared.global [%0], [%1], 16;" \
                 :: "r"(smem_u32), "l"(gptr) : "memory")
#define CPA_COMMIT() asm volatile("cp.async.commit_group;" ::: "memory")
#define CPA_WAIT(n)  asm volatile("cp.async.wait_group %0;" :: "n"(n) : "memory")

// swizzle: 16B chunk c of row r placed at chunk (c ^ (r&7)); 128-B rows
__device__ __forceinline__ uint32_t tile_off(int row, int c) {
    return (uint32_t)(row * 128 + ((c ^ (row & 7)) << 4));
}

#define LDMX4(r0, r1, r2, r3, addr) \
    asm volatile("ldmatrix.sync.aligned.m8n8.x4.shared.b16 {%0,%1,%2,%3}, [%4];" \
        : "=r"(r0), "=r"(r1), "=r"(r2), "=r"(r3) : "r"(addr))

#define MMA16816(d, a, b0, b1) \
    asm volatile("mma.sync.aligned.m16n8k16.row.col.f32.bf16.bf16.f32 " \
        "{%0,%1,%2,%3}, {%4,%5,%6,%7}, {%8,%9}, {%0,%1,%2,%3};" \
        : "+f"((d)[0]), "+f"((d)[1]), "+f"((d)[2]), "+f"((d)[3]) \
        : "r"((a)[0]), "r"((a)[1]), "r"((a)[2]), "r"((a)[3]), "r"(b0), "r"(b1))

// convert 8 fp32 -> uint4 of bf16, accumulating stats
__device__ __forceinline__ uint4 cvt8(const float4 v0, const float4 v1,
                                      float& ss, float& su) {
    ss += v0.x*v0.x + v0.y*v0.y + v0.z*v0.z + v0.w*v0.w
        + v1.x*v1.x + v1.y*v1.y + v1.z*v1.z + v1.w*v1.w;
    su += v0.x + v0.y + v0.z + v0.w + v1.x + v1.y + v1.z + v1.w;
    union { __nv_bfloat162 h[4]; uint4 u; } pk;
    pk.h[0] = __float22bfloat162_rn(make_float2(v0.x, v0.y));
    pk.h[1] = __float22bfloat162_rn(make_float2(v0.z, v0.w));
    pk.h[2] = __float22bfloat162_rn(make_float2(v1.x, v1.y));
    pk.h[3] = __float22bfloat162_rn(make_float2(v1.z, v1.w));
    return pk.u;
}

// ---------------- kernel 1: FULLY FUSED stats + convert + dual bf16 GEMM --
// grid (KSPLIT, BB), 256 threads. Reads fp32 q,k,n exactly once.
// Per iteration (32 k-cols): cp.async fp32 slab -> SMEM, convert to bf16
// tiles (accumulating per-row sum/sumsq), then dual MMA (q.k^T and q.n^T)
// sharing the A fragments. 8 warps as 2x4: warptile 64(M) x 32(N), 2 outputs.
__device__ __forceinline__ void stage_load(uint32_t dst_stage,
                                           const float* q, const float* kk_,
                                           const float* nn_, int rowbase,
                                           int kelem, int tid) {
    #pragma unroll
    for (int h = 0; h < 12; h++) {
        int g = h * 256 + tid;             // 0..3071 16B chunks
        int o = g >> 10;                   // op: 0=q 1=k 2=n
        int idx = g & 1023;
        int r = idx >> 3;
        int c = idx & 7;
        const float* src = (o == 0 ? q : (o == 1 ? kk_ : nn_))
                           + (size_t)(rowbase + r) * FDD + kelem + c * 4;
        CPA16(dst_stage + o * F32OP + tile_off(r, c), src);
    }
}

__global__ __launch_bounds__(256, 1) void fused_k(const float* __restrict__ q,
                                                  const float* __restrict__ kk_,
                                                  const float* __restrict__ nn_) {
    extern __shared__ char smem[];
    int tid = threadIdx.x, wid = tid >> 5, lane = tid & 31;
    int wm = wid & 1, wn = wid >> 1;       // 2 x 4 warp grid
    int kc = blockIdx.x, b = blockIdx.y;
    int rowbase = b * NVV;
    int k0 = kc * KCHUNK;

    uint32_t sbase = s2u(smem);

    float accS[4][4][4], accL[4][4][4];
    #pragma unroll
    for (int mi = 0; mi < 4; mi++)
        #pragma unroll
        for (int ni = 0; ni < 4; ni++)
            #pragma unroll
            for (int e = 0; e < 4; e++) { accS[mi][ni][e] = 0.f; accL[mi][ni][e] = 0.f; }

    // stats accumulators: this thread owns row (tid&127), col-half (tid>>7)
    int crow = tid & 127, chalf = tid >> 7;
    float ssq = 0.f, suq = 0.f, ssk = 0.f, suk = 0.f, ssn = 0.f;

    // ldmatrix lane geometry (proven layout)
    int a_row = wm * 64 + (lane & 15);
    int a_chi = (lane >> 4);
    int b_row = wn * 32 + (lane & 7) + ((lane & 16) ? 8 : 0);
    int b_chi = (lane >> 3) & 1;

    // prologue: fill NSTG stages
    #pragma unroll
    for (int s = 0; s < NSTG; s++) {
        stage_load(sbase + s * (3 * F32OP), q, kk_, nn_, rowbase, k0 + s * SLAB, tid);
        CPA_COMMIT();
    }

    for (int it = 0; it < NITER; it++) {
        // 1. stage 'it' ready
        CPA_WAIT(NSTG - 1);
        __syncthreads();

        // 2. convert fp32 stage -> bf16 tiles, accumulate stats
        {
            uint32_t fst = sbase + (it % NSTG) * (3 * F32OP);
            const char* fbase = smem + (it % NSTG) * (3 * F32OP);
            #pragma unroll
            for (int o = 0; o < 3; o++) {
                const char* f32 = fbase + o * F32OP;
                char* b16 = smem + OFF_B16 + o * F32OP;
                float dss = 0.f, dsu = 0.f;
                #pragma unroll
                for (int i = 0; i < 2; i++) {
                    float4 va = *(const float4*)(f32 + tile_off(crow, chalf * 4 + 2 * i));
                    float4 vb = *(const float4*)(f32 + tile_off(crow, chalf * 4 + 2 * i + 1));
                    *(uint4*)(b16 + tile_off(crow, chalf * 2 + i)) = cvt8(va, vb, dss, dsu);
                }
                if (o == 0)      { ssq += dss; suq += dsu; }
                else if (o == 1) { ssk += dss; suk += dsu; }
                else             { ssn += dss; }
            }
            (void)fst;
        }
        __syncthreads();

        // 3. prefetch stage it+NSTG (exactly one commit per iteration)
        int nxt = it + NSTG;
        if (nxt < NITER)
            stage_load(sbase + (nxt % NSTG) * (3 * F32OP), q, kk_, nn_,
                       rowbase, k0 + nxt * SLAB, tid);
        CPA_COMMIT();

        // 4. dual MMA from bf16 tiles (A shared between S and L)
        uint32_t smA  = sbase + OFF_B16;
        uint32_t smBk = smA + F32OP;
        uint32_t smBn = smBk + F32OP;
        #pragma unroll
        for (int kk = 0; kk < 2; kk++) {     // K=32 -> two K=16 steps
            uint32_t af[4][4];
            #pragma unroll
            for (int mi = 0; mi < 4; mi++)
                LDMX4(af[mi][0], af[mi][1], af[mi][2], af[mi][3],
                      smA + tile_off(a_row + mi * 16, kk * 2 + a_chi));
            uint32_t bk[2][4], bn[2][4];
            #pragma unroll
            for (int nh = 0; nh < 2; nh++) {
                LDMX4(bk[nh][0], bk[nh][1], bk[nh][2], bk[nh][3],
                      smBk + tile_off(b_row + nh * 16, kk * 2 + b_chi));
                LDMX4(bn[nh][0], bn[nh][1], bn[nh][2], bn[nh][3],
                      smBn + tile_off(b_row + nh * 16, kk * 2 + b_chi));
            }
            #pragma unroll
            for (int mi = 0; mi < 4; mi++)
                #pragma unroll
                for (int ni = 0; ni < 4; ni++) {
                    MMA16816(accS[mi][ni], af[mi],
                             bk[ni >> 1][(ni & 1) * 2], bk[ni >> 1][(ni & 1) * 2 + 1]);
                    MMA16816(accL[mi][ni], af[mi],
                             bn[ni >> 1][(ni & 1) * 2], bn[ni >> 1][(ni & 1) * 2 + 1]);
                }
        }
        __syncthreads();                     // bf16 tiles reusable next iter
    }

    // ---- stats write-out: combine the two col-halves of each row ----
    {
        float* st = (float*)(smem + OFF_STAT);
        st[0 * 256 + tid] = ssq;
        st[1 * 256 + tid] = suq;
        st[2 * 256 + tid] = ssk;
        st[3 * 256 + tid] = suk;
        st[4 * 256 + tid] = ssn;
        __syncthreads();
        if (tid < 128) {
            int gr = rowbase + tid;
            g_ssp[(0 * KSPLIT + kc) * ROWS_TOT + gr] = st[0*256+tid] + st[0*256+tid+128];
            g_sup[(0 * KSPLIT + kc) * ROWS_TOT + gr] = st[1*256+tid] + st[1*256+tid+128];
            g_ssp[(1 * KSPLIT + kc) * ROWS_TOT + gr] = st[2*256+tid] + st[2*256+tid+128];
            g_sup[(1 * KSPLIT + kc) * ROWS_TOT + gr] = st[3*256+tid] + st[3*256+tid+128];
            g_ssp[(2 * KSPLIT + kc) * ROWS_TOT + gr] = st[4*256+tid] + st[4*256+tid+128];
        }
    }

    // ---- GEMM epilogue: write fp32 partials for both outputs ----
    float* outS = g_Sp + ((size_t)kc * BB + b) * (NVV * NVV);
    float* outL = g_Lp + ((size_t)kc * BB + b) * (NVV * NVV);
    int gr2 = lane >> 2, tc = lane & 3;
    #pragma unroll
    for (int mi = 0; mi < 4; mi++) {
        #pragma unroll
        for (int ni = 0; ni < 4; ni++) {
            int r0 = wm * 64 + mi * 16 + gr2;
            int col = wn * 32 + ni * 8 + tc * 2;
            *(float2*)&outS[(size_t)r0 * NVV + col] =
                make_float2(accS[mi][ni][0], accS[mi][ni][1]);
            *(float2*)&outS[(size_t)(r0 + 8) * NVV + col] =
                make_float2(accS[mi][ni][2], accS[mi][ni][3]);
            *(float2*)&outL[(size_t)r0 * NVV + col] =
                make_float2(accL[mi][ni][0], accL[mi][ni][1]);
            *(float2*)&outL[(size_t)(r0 + 8) * NVV + col] =
                make_float2(accL[mi][ni][2], accL[mi][ni][3]);
        }
    }
}

// ---------------- kernel 2: fused stats-reduce + normalize + loss --------
// grid (16, BB): 8 rows of the 128x128 matrices per CTA. Reads the K-split
// partials directly (L2-resident); reduces per-chunk stats inline.
__global__ __launch_bounds__(256) void epi3_k() {
    int chunk = blockIdx.x, b = blockIdx.y, tid = threadIdx.x;
    __shared__ float invq[NVV], invk[NVV], invn[NVV];
    __shared__ float sqv[NVV], skv[NVV], dqk_d[NVV], dkq_d[NVV], sdiag[NVV];

    if (tid < NVV) {
        int gr = b * NVV + tid;
        float ssq = 0.f, ssk = 0.f, ssn = 0.f, suq = 0.f, suk = 0.f;
        #pragma unroll
        for (int p = 0; p < KSPLIT; p++) {
            ssq += g_ssp[(0 * KSPLIT + p) * ROWS_TOT + gr];
            ssk += g_ssp[(1 * KSPLIT + p) * ROWS_TOT + gr];
            ssn += g_ssp[(2 * KSPLIT + p) * ROWS_TOT + gr];
            suq += g_sup[(0 * KSPLIT + p) * ROWS_TOT + gr];
            suk += g_sup[(1 * KSPLIT + p) * ROWS_TOT + gr];
        }
        float iq = 1.f / fmaxf(sqrtf(ssq), 1e-12f);
        float ik = 1.f / fmaxf(sqrtf(ssk), 1e-12f);
        invq[tid] = iq; invk[tid] = ik;
        invn[tid] = 1.f / fmaxf(sqrtf(ssn), 1e-12f);
        float sq = suq * iq, sk = suk * ik;
        sqv[tid] = sq; skv[tid] = sk;
        float sr = 0.f;
        #pragma unroll
        for (int p = 0; p < KSPLIT; p++)
            sr += g_Sp[(size_t)(p * BB + b) * (NVV * NVV) + tid * (NVV + 1)];
        float Sii = sr * iq * ik;
        sdiag[tid] = Sii;
        dqk_d[tid] = sqrtf(fmaxf(2.f - 2.f * Sii + 2.f * EPSF * (sq - sk) + CONSTE, 0.f));
        dkq_d[tid] = sqrtf(fmaxf(2.f - 2.f * Sii + 2.f * EPSF * (sk - sq) + CONSTE, 0.f));
    }
    __syncthreads();

    const float* Sp0 = g_Sp + (size_t)b * (NVV * NVV);
    const float* Lp0 = g_Lp + (size_t)b * (NVV * NVV);
    const size_t PST = (size_t)BB * NVV * NVV;     // stride between K-split slabs

    float smacc = 0.f, triacc = 0.f, cycacc = 0.f, ceacc = 0.f;
    #pragma unroll
    for (int h = 0; h < 4; h++) {
        int idx = h * 256 + tid;           // 0..1023 over 8 rows x 128 cols
        int il = idx >> 7, j = idx & 127;
        int i = chunk * 8 + il;
        float sr = 0.f;
        #pragma unroll
        for (int p = 0; p < KSPLIT; p++) sr += Sp0[p * PST + i * NVV + j];
        float Sij = sr * invq[i] * invk[j];
        if (i == j) {
            float d = Sij - 1.f; smacc += d * d;
        } else {
            smacc += Sij * Sij;
            float st = 0.f;
            #pragma unroll
            for (int p = 0; p < KSPLIT; p++) st += Sp0[p * PST + j * NVV + i];
            float Sji = st * invq[j] * invk[i];
            cycacc += fabsf(Sij - Sji);
            // tri1: anc=q_i, pos=k_i, neg=k_j
            float dq = sqrtf(fmaxf(2.f - 2.f * Sij + 2.f * EPSF * (sqv[i] - skv[j]) + CONSTE, 0.f));
            triacc += fmaxf(dqk_d[i] - dq + MARGINF, 0.f);
            // tri2 reindexed over (i,j): relu(dkq[j] - d(S_ij; sk[j], sq[i]) + M)
            float dk = sqrtf(fmaxf(2.f - 2.f * Sij + 2.f * EPSF * (skv[j] - sqv[i]) + CONSTE, 0.f));
            triacc += fmaxf(dkq_d[j] - dk + MARGINF, 0.f);
        }
    }

    // InfoNCE: warp w handles row chunk*8 + w (129 logits)
    int lane = tid & 31, w = tid >> 5;
    {
        int i = chunk * 8 + w;
        float iq = invq[i];
        float lpos = sdiag[i] * TINV;
        float mx = lpos;
        float lg[4];
        #pragma unroll
        for (int m = 0; m < 4; m++) {
            int j = lane + m * 32;
            float lr = 0.f;
            #pragma unroll
            for (int p = 0; p < KSPLIT; p++) lr += Lp0[p * PST + i * NVV + j];
            lg[m] = lr * iq * invn[j] * TINV;
            mx = fmaxf(mx, lg[m]);
        }
        #pragma unroll
        for (int o = 16; o > 0; o >>= 1) mx = fmaxf(mx, __shfl_xor_sync(0xffffffffu, mx, o));
        float se = (lane == 0) ? expf(lpos - mx) : 0.f;
        #pragma unroll
        for (int m = 0; m < 4; m++) se += expf(lg[m] - mx);
        #pragma unroll
        for (int o = 16; o > 0; o >>= 1) se += __shfl_xor_sync(0xffffffffu, se, o);
        if (lane == 0) ceacc = mx + logf(se) - lpos;
    }

    __shared__ float red[4][8];
    #pragma unroll
    for (int o = 16; o > 0; o >>= 1) {
        smacc  += __shfl_xor_sync(0xffffffffu, smacc,  o);
        triacc += __shfl_xor_sync(0xffffffffu, triacc, o);
        cycacc += __shfl_xor_sync(0xffffffffu, cycacc, o);
        ceacc  += __shfl_xor_sync(0xffffffffu, ceacc,  o);
    }
    if (lane == 0) { red[0][w] = smacc; red[1][w] = triacc; red[2][w] = cycacc; red[3][w] = ceacc; }
    __syncthreads();
    if (tid == 0) {
        float a = 0.f, t = 0.f, c = 0.f, e = 0.f;
        #pragma unroll
        for (int i = 0; i < 8; i++) { a += red[0][i]; t += red[1][i]; c += red[2][i]; e += red[3][i]; }
        float* p = &g_parts2[(b * 16 + chunk) * 4];
        p[0] = a; p[1] = t; p[2] = c; p[3] = e;
    }
}

// ---------------- kernel 3: parallel final combine ------------------------
// 256 threads reduce the 1024 weighted g_parts2 entries (weights encode the
// reference's cumsum-across-batches tri bug), then fan out the output write.
__global__ __launch_bounds__(256) void final2_k(float* out, int out_size) {
    int tid = threadIdx.x;
    float acc = 0.f;
    #pragma unroll
    for (int h = 0; h < 4; h++) {
        int e = h * 256 + tid;             // 0..1023 over (b, chunk, comp)
        int b = e >> 6;                    // 16 chunks * 4 comps = 64 per batch
        int comp = e & 3;
        float p = g_parts2[e];
        float w;
        if (comp == 1)      w = (float)(BB - b) / (float)(2 * NVV * (NVV - 1));
        else if (comp == 2) w = 1.f / (float)(NVV * (NVV - 1));
        else                w = 1.f / (float)(NVV * NVV);
        acc += w * p;
    }
    __shared__ float red[8];
    int lane = tid & 31, w = tid >> 5;
    #pragma unroll
    for (int o = 16; o > 0; o >>= 1) acc += __shfl_xor_sync(0xffffffffu, acc, o);
    if (lane == 0) red[w] = acc;
    __syncthreads();
    __shared__ float s_ssl;
    if (tid == 0) {
        float t = 0.f;
        #pragma unroll
        for (int i = 0; i < 8; i++) t += red[i];
        s_ssl = t;
    }
    __syncthreads();
    float v = s_ssl;
    for (int i = tid; i < out_size; i += 256) out[i] = v;
}

// ---------------- launch -----------------------------------------------
extern "C" void kernel_launch(void* const* d_in, const int* in_sizes, int n_in,
                              void* d_out, int out_size) {
    const float* q = (const float*)d_in[0];
    const float* k = (const float*)d_in[1];
    const float* n = (const float*)d_in[2];
    // d_in[3] = num_gt; fixed at 128 == NV for these shapes.

    cudaFuncSetAttribute(fused_k, cudaFuncAttributeMaxDynamicSharedMemorySize, SMEM_TOT);

    dim3 gg(KSPLIT, BB);
    fused_k<<<gg, 256, SMEM_TOT>>>(q, k, n);
    dim3 ge(16, BB);
    epi3_k<<<ge, 256>>>();
    final2_k<<<1, 256>>>((float*)d_out, out_size);
}